// round 15
// baseline (speedup 1.0000x reference)
#include <cuda_runtime.h>

static constexpr int B = 4096;
static constexpr int K = 1024;
static constexpr int C = 10;
static constexpr int M = 19;

// Block = 64 b x 8 warps, 256 threads. Lane owns a b-PAIR (int2 loads).
// Histogram in 2 copies (warp parity) -> 4 warps collide per address, not 8.
static constexpr int NB      = 64;
static constexpr int NW      = 8;
static constexpr int THREADS = NW * 32;           // 256
static constexpr int KSPLIT  = 8;
static constexpr int KBLK    = K / KSPLIT;        // 128
static constexpr int KCHUNK  = KBLK / NW;         // 16 iters (32 samples/thread)

static constexpr int CSTR    = 101;               // row stride: bank=5*row+cell, conflict-free
static constexpr int CNT_F   = 2 * NB * CSTR;     // 2 copies x 64 rows
static constexpr int SMEM_B  = CNT_F * 4;         // 51712 B dynamic

__device__ float g_scratch[B * M];    // zero-init; re-zeroed by finishing block
__device__ int   g_ticket[B / NB];    // zero-init; reset by finishing block

__global__ __launch_bounds__(THREADS)
void ised_kernel(const float* __restrict__ x1,
                 const float* __restrict__ x2,
                 const int*   __restrict__ idx1,
                 const int*   __restrict__ idx2,
                 float*       __restrict__ out)
{
    extern __shared__ unsigned cnt[];     // [copy][row][cell], row = h*32 + lane
    __shared__ float xs1[NB][C];
    __shared__ float xs2[NB][C];
    __shared__ float rowsum[NB][M + 1];
    __shared__ int   s_last;

    const int tid = threadIdx.x;
    const int b0  = blockIdx.x * NB;
    const int k0  = blockIdx.y * KBLK;

    // ---- Zero histograms; stage x rows ----
    for (int e = tid; e < CNT_F; e += THREADS) {
        cnt[e] = 0u;
    }
    for (int e = tid; e < NB * C; e += THREADS) {
        const int bl = e / C;
        const int i  = e - bl * C;
        xs1[bl][i] = __ldg(&x1[(b0 + bl) * C + i]);
        xs2[bl][i] = __ldg(&x2[(b0 + bl) * C + i]);
    }
    __syncthreads();

    // ---- Hot loop: int2 b-pair, fire-and-forget atomics, 2 copies ----
    const int lane = tid & 31;
    const int w    = tid >> 5;
    const int copy = w & 1;
    const int b    = b0 + 2 * lane;               // 8B aligned

    const int2* __restrict__ p1 =
        (const int2*)(idx1 + (size_t)(k0 + w * KCHUNK) * B + b);
    const int2* __restrict__ p2 =
        (const int2*)(idx2 + (size_t)(k0 + w * KCHUNK) * B + b);

    // b_local = 2*lane+h  ->  row = h*32 + lane  (keeps ATOMS banks distinct)
    unsigned* __restrict__ cx = cnt + (copy * NB + lane) * CSTR;        // h=0
    unsigned* __restrict__ cy = cnt + (copy * NB + 32 + lane) * CSTR;   // h=1

    #pragma unroll 4
    for (int k = 0; k < KCHUNK; k++) {
        const int2 a = __ldg(&p1[(size_t)k * (B / 2)]);
        const int2 c = __ldg(&p2[(size_t)k * (B / 2)]);
        atomicAdd(&cx[a.x * 10 + c.x], 1u);
        atomicAdd(&cy[a.y * 10 + c.y], 1u);
    }
    __syncthreads();

    // ---- Epilogue: result[b][m] = sum_{i+j=m} xs1[i]*xs2[j]*(cnt0+cnt1) ----
    for (int e = tid; e < NB * M; e += THREADS) {
        const int bl  = e & (NB - 1);
        const int m   = e >> 6;
        const int row = (bl & 1) * 32 + (bl >> 1);
        const unsigned* __restrict__ r0 = cnt + row * CSTR;
        const unsigned* __restrict__ r1 = cnt + (NB + row) * CSTR;
        const int ilo = (m > 9) ? (m - 9) : 0;
        const int ihi = (m < 9) ? m : 9;
        float v = 0.0f;
        for (int i = ilo; i <= ihi; i++) {
            const int cell = i * 10 + (m - i);
            v += xs1[bl][i] * xs2[bl][m - i] * (float)(r0[cell] + r1[cell]);
        }
        atomicAdd(&g_scratch[(b0 + bl) * M + m], v);
    }

    // ---- Ticket: last KSPLIT-block for this row-group finishes the rows ----
    __threadfence();
    __syncthreads();
    if (tid == 0) {
        s_last = (atomicAdd(&g_ticket[blockIdx.x], 1) == KSPLIT - 1);
    }
    __syncthreads();
    if (!s_last) return;

    for (int e = tid; e < NB * M; e += THREADS) {
        const int bl = e & (NB - 1);
        const int m  = e >> 6;
        rowsum[bl][m] = __ldcg(&g_scratch[(b0 + bl) * M + m]);
    }
    __syncthreads();

    if (tid < NB) {
        float sq = 0.0f;
        #pragma unroll
        for (int m = 0; m < M; m++) {
            const float v = rowsum[tid][m];
            sq += v * v;
        }
        rowsum[tid][M] = 1.0f / fmaxf(sqrtf(sq), 1e-12f);
    }
    __syncthreads();

    for (int e = tid; e < NB * M; e += THREADS) {
        const int bl = e & (NB - 1);
        const int m  = e >> 6;
        out[(size_t)(b0 + bl) * M + m] = rowsum[bl][m] * rowsum[bl][M];
        __stcg(&g_scratch[(b0 + bl) * M + m], 0.0f);   // reset for next replay
    }
    if (tid == 0) {
        g_ticket[blockIdx.x] = 0;
    }
}

extern "C" void kernel_launch(void* const* d_in, const int* in_sizes, int n_in,
                              void* d_out, int out_size)
{
    const float* x1   = (const float*)d_in[0];   // [B, C]
    const float* x2   = (const float*)d_in[1];   // [B, C]
    const int*   idx1 = (const int*)d_in[2];     // [K, B]
    const int*   idx2 = (const int*)d_in[3];     // [K, B]
    float*       out  = (float*)d_out;           // [B, M]

    (void)in_sizes; (void)n_in; (void)out_size;

    cudaFuncSetAttribute(ised_kernel,
                         cudaFuncAttributeMaxDynamicSharedMemorySize, SMEM_B);

    dim3 grid(B / NB, KSPLIT);
    ised_kernel<<<grid, THREADS, SMEM_B>>>(x1, x2, idx1, idx2, out);
}